// round 17
// baseline (speedup 1.0000x reference)
#include <cuda_runtime.h>
#include <cuda_fp16.h>
#include <cstdint>
#include <cstddef>

// ---------------- problem constants ----------------
#define S_LEN  2048
#define HID    2048
#define NHEAD  16
#define NKVH   4
#define HDIM   128
#define BATCH  2
#define ROWS   (BATCH * S_LEN)      // 4096
#define SCALE  0.08838834764831845f // 1/sqrt(128)

// ---------------- scratch (static device memory; no allocations) ----------------
__device__ float2 g_rope_tab[(size_t)S_LEN * 64];

// fp16 operands
__device__ unsigned short g_xh[(size_t)ROWS * HID];
__device__ unsigned short g_oh[(size_t)ROWS * HID];
__device__ unsigned short g_wqh[(size_t)2048 * HID];   // pre-scaled by SCALE
__device__ unsigned short g_wkh[(size_t)512 * HID];
__device__ unsigned short g_wvh[(size_t)512 * HID];
__device__ unsigned short g_woh[(size_t)2048 * HID];
__device__ unsigned short g_qh[(size_t)ROWS * NHEAD * HDIM];   // roped, scaled
__device__ unsigned short g_kh[(size_t)ROWS * NKVH * HDIM];    // roped
__device__ unsigned short g_vth[(size_t)BATCH * NKVH * HDIM * S_LEN];

// ================= mma.sync / ldmatrix / cp.async helpers =================
__device__ __forceinline__ void mma_f16(float* c, const uint32_t* a, const uint32_t* b)
{
    asm volatile(
        "mma.sync.aligned.m16n8k16.row.col.f32.f16.f16.f32 "
        "{%0,%1,%2,%3}, {%4,%5,%6,%7}, {%8,%9}, {%0,%1,%2,%3};"
        : "+f"(c[0]), "+f"(c[1]), "+f"(c[2]), "+f"(c[3])
        : "r"(a[0]), "r"(a[1]), "r"(a[2]), "r"(a[3]), "r"(b[0]), "r"(b[1]));
}
__device__ __forceinline__ void ldsm_x4(uint32_t* r, uint32_t addr)
{
    asm volatile("ldmatrix.sync.aligned.m8n8.x4.shared.b16 {%0,%1,%2,%3}, [%4];"
        : "=r"(r[0]), "=r"(r[1]), "=r"(r[2]), "=r"(r[3]) : "r"(addr));
}
__device__ __forceinline__ uint32_t smem_u32(const void* p) {
    uint32_t a;
    asm("{ .reg .u64 t; cvta.to.shared.u64 t, %1; cvt.u32.u64 %0, t; }" : "=r"(a) : "l"(p));
    return a;
}
__device__ __forceinline__ void cp_async16(uint32_t dst, const void* src) {
    asm volatile("cp.async.cg.shared.global [%0], [%1], 16;" :: "r"(dst), "l"(src));
}
#define CP_COMMIT() asm volatile("cp.async.commit_group;" ::: "memory")
#define CP_WAIT0()  asm volatile("cp.async.wait_group 0;" ::: "memory")

__device__ __forceinline__ unsigned short f2h(float v) {
    __half h = __float2half_rn(v);
    return *(unsigned short*)&h;
}
__device__ __forceinline__ uint32_t pack2h(float a, float b) {
    __half2 h = __floats2half2_rn(a, b);
    return *(uint32_t*)&h;
}

// ================= conversion kernels =================
__global__ void convert_h(const float* __restrict__ src,
                          unsigned short* __restrict__ dst, int total)
{
    int i = blockIdx.x * blockDim.x + threadIdx.x;
    if (i >= total) return;
    dst[i] = f2h(src[i]);
}

// weight transposes + rope table in one launch.
// z: 0=wq(scaled) 1=wk 2=wv 3=wo 4=rope table
__global__ void prep_all(const float* __restrict__ wq, const float* __restrict__ wk,
                         const float* __restrict__ wv, const float* __restrict__ wo,
                         unsigned short* __restrict__ wqh, unsigned short* __restrict__ wkh,
                         unsigned short* __restrict__ wvh, unsigned short* __restrict__ woh)
{
    const int z = blockIdx.z;
    if (z == 4) {
        // rope table: 131072 entries; grid x*y = 64*64 blocks of 256 threads covers it
        int blk = blockIdx.y * gridDim.x + blockIdx.x;
        int idx = blk * 256 + threadIdx.y * 32 + threadIdx.x;
        if (idx >= S_LEN * 64) return;
        int d = idx & 63, pos = idx >> 6;
        double inv = pow(10000.0, -((double)(2 * d)) / 128.0);
        double cd, sd;
        sincos((double)pos * inv, &sd, &cd);
        g_rope_tab[idx] = make_float2((float)cd, (float)sd);
        return;
    }

    const float* src; unsigned short* dst; int N; float scale = 1.0f;
    if (z == 0)      { src = wq; dst = wqh; N = 2048; scale = SCALE; }
    else if (z == 1) { src = wk; dst = wkh; N = 512; }
    else if (z == 2) { src = wv; dst = wvh; N = 512; }
    else             { src = wo; dst = woh; N = 2048; }
    if (blockIdx.x * 32 >= N) return;

    __shared__ float t[32][33];
    const int n0 = blockIdx.x * 32, k0 = blockIdx.y * 32;
    const int tx = threadIdx.x, ty = threadIdx.y;  // (32, 8)
    #pragma unroll
    for (int i = 0; i < 4; i++)
        t[ty + i * 8][tx] = src[(size_t)(k0 + ty + i * 8) * N + n0 + tx];
    __syncthreads();
    #pragma unroll
    for (int i = 0; i < 4; i++) {
        int n = ty + i * 8;
        dst[(size_t)(n0 + n) * HID + k0 + tx] = f2h(t[tx][n] * scale);
    }
}

// ================= fp16 GEMM: 256 thr, 128x128 tile, 2-stage, single-sync =================
// modes: 0 = fp32 C; 1 = rope + fp16 row-major; 2 = fp16 transposed (vth)
#define KTILE    64
#define NT_STEPS (HID / KTILE)      // 32
#define APITCH   72                 // u16 smem pitch (144B)
#define TILE_U16 (128 * APITCH)     // 9216
#define BUF_U16  (2 * TILE_U16)     // A + B per stage
#define GEMM_SMEM (2 * BUF_U16 * 2) // 73728 B
#define PITCHF   132                // fp32 staging pitch (epilogue)

__device__ void gemm_mma_body(const unsigned short* __restrict__ Ah,
                              const unsigned short* __restrict__ Bh,
                              int row0, int col0,
                              int mode,
                              float* __restrict__ C, int ldc,            // mode 0
                              unsigned short* __restrict__ O16, int ldo, // mode 1
                              unsigned short* __restrict__ VT, int bg)   // mode 2
{
    extern __shared__ unsigned short sm[];
    const uint32_t sbase = smem_u32(sm);
    const int tid  = threadIdx.x;
    const int wid  = tid >> 5;
    const int lane = tid & 31;
    const int wm   = wid & 1;
    const int wn   = wid >> 1;
    const int g    = lane >> 2;
    const int tq   = lane & 3;

    const int lr   = lane & 7;
    const int oaR  = (lane & 8)  ? 8 : 0;
    const int oaC  = (lane & 16) ? 8 : 0;
    const int obR  = (lane & 16) ? 8 : 0;
    const int obC  = (lane & 8)  ? 8 : 0;
    const int rowA0 = wm * 64 + lr + oaR;
    const int rowB0 = wn * 32 + lr + obR;

    const int r    = tid >> 1;
    const int half = tid & 1;
    const unsigned short* pA = Ah + (size_t)(row0 + r) * HID + half * 32;
    const unsigned short* pB = Bh + (size_t)(col0 + r) * HID + half * 32;
    const uint32_t dsoff = 2u * (uint32_t)(r * APITCH + half * 32);

    float acc[4][4][4];
    #pragma unroll
    for (int mi = 0; mi < 4; mi++)
        #pragma unroll
        for (int ni = 0; ni < 4; ni++)
            #pragma unroll
            for (int e = 0; e < 4; e++) acc[mi][ni][e] = 0.0f;

    auto issue = [&](int t, int buf) {
        const int k0 = t * KTILE;
        const uint32_t a0 = sbase + 2u * (uint32_t)(buf * BUF_U16) + dsoff;
        const uint32_t b0 = a0 + 2u * TILE_U16;
        cp_async16(a0,      pA + k0);
        cp_async16(a0 + 16, pA + k0 + 8);
        cp_async16(a0 + 32, pA + k0 + 16);
        cp_async16(a0 + 48, pA + k0 + 24);
        cp_async16(b0,      pB + k0);
        cp_async16(b0 + 16, pB + k0 + 8);
        cp_async16(b0 + 32, pB + k0 + 16);
        cp_async16(b0 + 48, pB + k0 + 24);
    };

    issue(0, 0);
    CP_COMMIT();

    for (int t = 0; t < NT_STEPS; t++) {
        const int cur = t & 1;
        CP_WAIT0();              // tile t complete (only pending group)
        __syncthreads();         // all warps done with tile t-1, tile t visible
        if (t + 1 < NT_STEPS) {
            issue(t + 1, cur ^ 1);
            CP_COMMIT();
        }

        const uint32_t aH = sbase + 2u * (uint32_t)(cur * BUF_U16);
        const uint32_t bH = aH + 2u * TILE_U16;

        #pragma unroll
        for (int ks = 0; ks < KTILE; ks += 16) {
            uint32_t bhf[2][4];
            #pragma unroll
            for (int jj = 0; jj < 2; jj++)
                ldsm_x4(bhf[jj], bH + 2u * (uint32_t)((rowB0 + jj * 16) * APITCH + ks + obC));
            #pragma unroll
            for (int mi = 0; mi < 4; mi++) {
                uint32_t ahf[4];
                ldsm_x4(ahf, aH + 2u * (uint32_t)((rowA0 + mi * 16) * APITCH + ks + oaC));
                #pragma unroll
                for (int jj = 0; jj < 2; jj++) {
                    mma_f16(acc[mi][2*jj],   ahf, &bhf[jj][0]);
                    mma_f16(acc[mi][2*jj+1], ahf, &bhf[jj][2]);
                }
            }
        }
    }

    if (mode == 0) {
        #pragma unroll
        for (int mi = 0; mi < 4; mi++) {
            const int mrow = row0 + wm * 64 + mi * 16 + g;
            #pragma unroll
            for (int ni = 0; ni < 4; ni++) {
                const int ncol = col0 + wn * 32 + ni * 8 + tq * 2;
                *(float2*)(C + (size_t)mrow * ldc + ncol)       = make_float2(acc[mi][ni][0], acc[mi][ni][1]);
                *(float2*)(C + (size_t)(mrow + 8) * ldc + ncol) = make_float2(acc[mi][ni][2], acc[mi][ni][3]);
            }
        }
        return;
    }

    __syncthreads();   // operand smem reads done before staging overwrite

    // ---- stage fp32 accumulators into smem ----
    float* stf = (float*)sm;
    #pragma unroll
    for (int mi = 0; mi < 4; mi++) {
        const int rl = wm * 64 + mi * 16 + g;
        #pragma unroll
        for (int ni = 0; ni < 4; ni++) {
            const int cl = wn * 32 + ni * 8 + tq * 2;
            stf[rl * PITCHF + cl]           = acc[mi][ni][0];
            stf[rl * PITCHF + cl + 1]       = acc[mi][ni][1];
            stf[(rl + 8) * PITCHF + cl]     = acc[mi][ni][2];
            stf[(rl + 8) * PITCHF + cl + 1] = acc[mi][ni][3];
        }
    }
    __syncthreads();

    if (mode == 1) {
        const int rr = tid >> 1;
        const int dbase = (tid & 1) * 32;
        const int pos = (row0 + rr) & (S_LEN - 1);
        unsigned short b1[32], b2[32];
        #pragma unroll
        for (int i = 0; i < 32; i++) {
            const int d = dbase + i;
            float x1 = stf[rr * PITCHF + d];
            float x2 = stf[rr * PITCHF + d + 64];
            float2 cs = g_rope_tab[pos * 64 + d];
            b1[i] = f2h(x1 * cs.x - x2 * cs.y);
            b2[i] = f2h(x2 * cs.x + x1 * cs.y);
        }
        unsigned short* o1 = O16 + (size_t)(row0 + rr) * ldo + col0 + dbase;
        #pragma unroll
        for (int j = 0; j < 4; j++) *(uint4*)(o1 + j * 8)      = ((uint4*)b1)[j];
        #pragma unroll
        for (int j = 0; j < 4; j++) *(uint4*)(o1 + 64 + j * 8) = ((uint4*)b2)[j];
    } else {
        const int d   = tid >> 1;
        const int kh2 = tid & 1;
        unsigned short vb[64];
        #pragma unroll
        for (int i = 0; i < 64; i++)
            vb[i] = f2h(stf[(kh2 * 64 + i) * PITCHF + d]);
        unsigned short* o = VT + ((size_t)bg * 128 + d) * S_LEN + (row0 & (S_LEN - 1)) + kh2 * 64;
        #pragma unroll
        for (int j = 0; j < 8; j++) *(uint4*)(o + j * 8) = ((uint4*)vb)[j];
    }
}

// fused QKV: grid.x 0..15 -> q heads, 16..19 -> k heads, 20..23 -> v heads
__global__ void __launch_bounds__(256, 2)
qkv_tc(const unsigned short* xh,
       const unsigned short* wqh, const unsigned short* wkh, const unsigned short* wvh,
       unsigned short* qh, unsigned short* kh, unsigned short* vth)
{
    const int bx = blockIdx.x;
    const int row0 = blockIdx.y * 128;
    if (bx < 16) {
        gemm_mma_body(xh, wqh, row0, bx * 128, 1, nullptr, 0, qh, 2048, nullptr, 0);
    } else if (bx < 20) {
        gemm_mma_body(xh, wkh, row0, (bx - 16) * 128, 1, nullptr, 0, kh, 512, nullptr, 0);
    } else {
        const int col0 = (bx - 20) * 128;
        const int bg = (row0 >> 11) * 4 + (col0 >> 7);
        gemm_mma_body(xh, wvh, row0, col0, 2, nullptr, 0, nullptr, 0, vth, bg);
    }
}

__global__ void __launch_bounds__(256, 2)
out_tc(const unsigned short* oh, const unsigned short* woh, float* C)
{
    gemm_mma_body(oh, woh, blockIdx.y * 128, blockIdx.x * 128, 0, C, 2048,
                  nullptr, 0, nullptr, 0);
}

// ================= flash attention: diagonal-paired q-blocks, single-sync =================
// grid (S/256, NH, B): CTA processes q-blocks {qx, 15-qx} -> uniform 34 tile-units.
#define AKP 136
#define AVP 72
#define STG_U16 (64 * AKP + 128 * AVP)   // 17920 u16 per stage
#define SVOFF   (64 * AKP)
#define ATT_SMEM (2 * STG_U16 * 2)       // 71680 B
#define NQB (S_LEN / 128)                // 16 q-blocks

__global__ void __launch_bounds__(256)
attn_mma(const unsigned short* __restrict__ Qh,
         const unsigned short* __restrict__ Kh,
         const unsigned short* __restrict__ Vth,
         unsigned short* __restrict__ Oh)
{
    const int qx = blockIdx.x;      // 0..7
    const int h  = blockIdx.y;
    const int b  = blockIdx.z;
    const int g4 = h >> 2;
    const int bg = b * 4 + g4;

    extern __shared__ unsigned short smu[];
    const uint32_t sbase = smem_u32(smu);

    const int tid  = threadIdx.x;   // 0..255
    const int wid  = tid >> 5;      // 0..7
    const int lane = tid & 31;
    const int gr   = lane >> 2;
    const int tq   = lane & 3;

    const int lr    = lane & 7;
    const int off8a = (lane & 8)  ? 8 : 0;
    const int off8b = (lane & 16) ? 8 : 0;

    const unsigned short* kh_base  = Kh  + ((size_t)(b * S_LEN) * 4 + g4) * 128;
    const unsigned short* vth_base = Vth + (size_t)bg * 128 * S_LEN;

    auto load_tile = [&](int kt, int buf) {
        const uint32_t sb = sbase + 2u * (uint32_t)(buf * STG_U16);
        const unsigned short* src_k = kh_base + (size_t)(kt * 64) * 512;
        #pragma unroll
        for (int i = 0; i < 4; i++) {
            int idx = tid + i * 256;
            int row = idx >> 4, seg = (idx & 15) * 8;
            cp_async16(sb + 2u * (uint32_t)(row * AKP + seg), src_k + (size_t)row * 512 + seg);
        }
        const unsigned short* src_v = vth_base + kt * 64;
        #pragma unroll
        for (int i = 0; i < 4; i++) {
            int idx = tid + i * 256;
            int row = idx >> 3, seg = (idx & 7) * 8;
            cp_async16(sb + 2u * (uint32_t)(SVOFF + row * AVP + seg), src_v + (size_t)row * S_LEN + seg);
        }
    };

    #pragma unroll 1
    for (int pass = 0; pass < 2; pass++) {
        const int qb = pass ? (NQB - 1 - qx) : qx;
        const int nkt = 2 * qb + 2;

        // issue tile-0 cp.async BEFORE the Q register loads so they overlap
        __syncthreads();   // protect smem buffers from previous pass's readers
        load_tile(0, 0);
        CP_COMMIT();

        // ---- Q fragments: direct fp16 loads (pre-scaled, pre-roped) ----
        const int q0 = qb * 128 + wid * 16;
        const int grow0 = q0 + gr;
        const int grow1 = q0 + gr + 8;
        const unsigned short* pq0 = Qh + (size_t)(b * S_LEN + grow0) * 2048 + h * 128;
        const unsigned short* pq1 = Qh + (size_t)(b * S_LEN + grow1) * 2048 + h * 128;
        uint32_t qhf[8][4];
        #pragma unroll
        for (int ks = 0; ks < 8; ks++) {
            qhf[ks][0] = *(const uint32_t*)(pq0 + 16 * ks + 2 * tq);
            qhf[ks][1] = *(const uint32_t*)(pq1 + 16 * ks + 2 * tq);
            qhf[ks][2] = *(const uint32_t*)(pq0 + 16 * ks + 2 * tq + 8);
            qhf[ks][3] = *(const uint32_t*)(pq1 + 16 * ks + 2 * tq + 8);
        }

        float o[16][4];
        #pragma unroll
        for (int j = 0; j < 16; j++)
            #pragma unroll
            for (int e = 0; e < 4; e++) o[j][e] = 0.0f;
        float m0 = -1e30f, m1 = -1e30f, l0 = 0.0f, l1 = 0.0f;

        for (int kt = 0; kt < nkt; kt++) {
            const int buf = kt & 1;
            CP_WAIT0();            // tile kt ready (only pending group)
            __syncthreads();       // all warps past tile kt-1; tile kt visible
            if (kt + 1 < nkt) {
                load_tile(kt + 1, buf ^ 1);
                CP_COMMIT();
            }

            const uint32_t stg = sbase + 2u * (uint32_t)(buf * STG_U16);

            // ---- scores ----
            float s[8][4];
            #pragma unroll
            for (int j = 0; j < 8; j++)
                #pragma unroll
                for (int e = 0; e < 4; e++) s[j][e] = 0.0f;

            #pragma unroll
            for (int jj = 0; jj < 4; jj++) {
                #pragma unroll
                for (int ks = 0; ks < 8; ks++) {
                    uint32_t khf[4];
                    ldsm_x4(khf, stg + 2u * (uint32_t)((16 * jj + off8b + lr) * AKP + 16 * ks + off8a));
                    mma_f16(s[2*jj],   qhf[ks], khf + 0);
                    mma_f16(s[2*jj+1], qhf[ks], khf + 2);
                }
            }

            // ---- causal mask (only last two tiles cross the diagonal) ----
            if (kt >= 2 * qb) {
                const int colbase = kt * 64;
                #pragma unroll
                for (int j = 0; j < 8; j++) {
                    int c0 = colbase + 8 * j + 2 * tq, c1 = c0 + 1;
                    if (c0 > grow0) s[j][0] = -1e30f;
                    if (c1 > grow0) s[j][1] = -1e30f;
                    if (c0 > grow1) s[j][2] = -1e30f;
                    if (c1 > grow1) s[j][3] = -1e30f;
                }
            }

            // ---- online softmax ----
            float mx0 = -1e30f, mx1 = -1e30f;
            #pragma unroll
            for (int j = 0; j < 8; j++) {
                mx0 = fmaxf(mx0, fmaxf(s[j][0], s[j][1]));
                mx1 = fmaxf(mx1, fmaxf(s[j][2], s[j][3]));
            }
            mx0 = fmaxf(mx0, __shfl_xor_sync(0xffffffffu, mx0, 1));
            mx0 = fmaxf(mx0, __shfl_xor_sync(0xffffffffu, mx0, 2));
            mx1 = fmaxf(mx1, __shfl_xor_sync(0xffffffffu, mx1, 1));
            mx1 = fmaxf(mx1, __shfl_xor_sync(0xffffffffu, mx1, 2));

            float mn0 = fmaxf(m0, mx0), mn1 = fmaxf(m1, mx1);
            float c0 = __expf(m0 - mn0), c1 = __expf(m1 - mn1);

            uint32_t ph[8][2];
            float sum0 = 0.0f, sum1 = 0.0f;
            #pragma unroll
            for (int j = 0; j < 8; j++) {
                float p0 = __expf(s[j][0] - mn0);
                float p1 = __expf(s[j][1] - mn0);
                float p2 = __expf(s[j][2] - mn1);
                float p3 = __expf(s[j][3] - mn1);
                sum0 += p0 + p1;
                sum1 += p2 + p3;
                ph[j][0] = pack2h(p0, p1);
                ph[j][1] = pack2h(p2, p3);
            }
            sum0 += __shfl_xor_sync(0xffffffffu, sum0, 1);
            sum0 += __shfl_xor_sync(0xffffffffu, sum0, 2);
            sum1 += __shfl_xor_sync(0xffffffffu, sum1, 1);
            sum1 += __shfl_xor_sync(0xffffffffu, sum1, 2);
            l0 = l0 * c0 + sum0;
            l1 = l1 * c1 + sum1;
            m0 = mn0; m1 = mn1;
            #pragma unroll
            for (int j = 0; j < 16; j++) {
                o[j][0] *= c0; o[j][1] *= c0;
                o[j][2] *= c1; o[j][3] *= c1;
            }

            // ---- PV ----
            #pragma unroll
            for (int ks = 0; ks < 4; ks++) {
                uint32_t ah4[4] = { ph[2*ks][0], ph[2*ks][1], ph[2*ks+1][0], ph[2*ks+1][1] };
                #pragma unroll
                for (int jj = 0; jj < 8; jj++) {
                    uint32_t vhf[4];
                    ldsm_x4(vhf, stg + 2u * (uint32_t)(SVOFF + (16 * jj + off8b + lr) * AVP + 16 * ks + off8a));
                    mma_f16(o[2*jj],   ah4, vhf + 0);
                    mma_f16(o[2*jj+1], ah4, vhf + 2);
                }
            }
        }

        // ---- epilogue: normalize, store fp16 ----
        const float inv0 = 1.0f / l0, inv1 = 1.0f / l1;
        const size_t rowA = (size_t)(b * S_LEN + grow0) * 2048 + h * 128;
        const size_t rowB = (size_t)(b * S_LEN + grow1) * 2048 + h * 128;
        #pragma unroll
        for (int j = 0; j < 16; j++) {
            const int col = 8 * j + 2 * tq;
            *(uint32_t*)(Oh + rowA + col) = pack2h(o[j][0] * inv0, o[j][1] * inv0);
            *(uint32_t*)(Oh + rowB + col) = pack2h(o[j][2] * inv1, o[j][3] * inv1);
        }
    }
}

// ================= launch =================
extern "C" void kernel_launch(void* const* d_in, const int* in_sizes, int n_in,
                              void* d_out, int out_size)
{
    const float* x  = (const float*)d_in[0];
    const float* wq = (const float*)d_in[1];
    const float* wk = (const float*)d_in[2];
    const float* wv = (const float*)d_in[3];
    const float* wo = (const float*)d_in[4];
    float* out = (float*)d_out;

    unsigned short *xh, *oh, *wqh, *wkh, *wvh, *woh, *qh, *kh, *vth;
    cudaGetSymbolAddress((void**)&xh, g_xh);
    cudaGetSymbolAddress((void**)&oh, g_oh);
    cudaGetSymbolAddress((void**)&wqh, g_wqh);
    cudaGetSymbolAddress((void**)&wkh, g_wkh);
    cudaGetSymbolAddress((void**)&wvh, g_wvh);
    cudaGetSymbolAddress((void**)&woh, g_woh);
    cudaGetSymbolAddress((void**)&qh, g_qh);
    cudaGetSymbolAddress((void**)&kh, g_kh);
    cudaGetSymbolAddress((void**)&vth, g_vth);

    cudaFuncSetAttribute(qkv_tc, cudaFuncAttributeMaxDynamicSharedMemorySize, GEMM_SMEM);
    cudaFuncSetAttribute(out_tc, cudaFuncAttributeMaxDynamicSharedMemorySize, GEMM_SMEM);
    cudaFuncSetAttribute(attn_mma, cudaFuncAttributeMaxDynamicSharedMemorySize, ATT_SMEM);

    // 0. operand conversion + weight transposes + rope table (2 launches)
    convert_h<<<(ROWS * HID + 255) / 256, 256>>>(x, xh, ROWS * HID);
    prep_all<<<dim3(64, 64, 5), dim3(32, 8)>>>(wq, wk, wv, wo, wqh, wkh, wvh, woh);

    // 1. fused QKV projections + rope + quantize + V-transpose
    qkv_tc<<<dim3(24, ROWS / 128), 256, GEMM_SMEM>>>(xh, wqh, wkh, wvh, qh, kh, vth);

    // 2. flash attention (diagonal-paired q-blocks, uniform load)
    attn_mma<<<dim3(S_LEN / 256, NHEAD, BATCH), 256, ATT_SMEM>>>(qh, kh, vth, oh);

    // 3. output projection
    out_tc<<<dim3(HID / 128, ROWS / 128), 256, GEMM_SMEM>>>(oh, woh, out);
}